// round 16
// baseline (speedup 1.0000x reference)
#include <cuda_runtime.h>
#include <cuda_bf16.h>
#include <cstdint>

#define NN 20000
#define DIN 128
#define HIDC 128
#define NHEADS 4
#define MAXM (NHEADS * HIDC)      // 512
#define EMAX 320000
#define ETOTMAX (EMAX + NN)

// -------------------- scratch (device globals) ------------------------------
__device__ float         g_h1 [NN * MAXM];            // f32 (final layer out)
__device__ __nv_bfloat16 g_hb0[NN * MAXM];            // bf16 layer outputs
__device__ __nv_bfloat16 g_hb1[NN * MAXM];
__device__ __nv_bfloat16 g_xb [NN * DIN];             // bf16 input x
__device__ __nv_bfloat16 g_wb [393216];               // bf16 weights (same layout)
__device__ __nv_bfloat16 g_xlh[NN * MAXM];
__device__ float         g_as [3 * NN * NHEADS];
__device__ float         g_ad [3 * NN * NHEADS];
__device__ float         g_pool[HIDC];
__device__ int           g_csr_src[ETOTMAX];
__device__ int           g_row_ptr[NN + 1];
__device__ int           g_cnt[NN];
__device__ int           g_cursor[NN];

// -------------------- helpers ----------------------------------------------
__device__ __forceinline__ uint32_t bf2_pack(float lo, float hi) {
    __nv_bfloat162 v = __float22bfloat162_rn(make_float2(lo, hi));
    return *(uint32_t*)&v;
}
__device__ __forceinline__ uint32_t smem_u32(const void* p) {
    return (uint32_t)__cvta_generic_to_shared(p);
}
__device__ __forceinline__ void cp16(uint32_t saddr, const void* g, int srcsz) {
    asm volatile("cp.async.cg.shared.global [%0], [%1], 16, %2;"
                 :: "r"(saddr), "l"(g), "r"(srcsz));
}
__device__ __forceinline__ void cp_commit() {
    asm volatile("cp.async.commit_group;");
}
template <int N> __device__ __forceinline__ void cp_wait() {
    asm volatile("cp.async.wait_group %0;" :: "n"(N));
}
__device__ __forceinline__ void edge_sd(const int* __restrict__ ei, int E, int e,
                                        int& s, int& d) {
    if (e < E) { s = ei[e]; d = ei[E + e]; }
    else       { s = d = e - E; }
}
__device__ __forceinline__ void ldsm_x4(uint32_t* r, uint32_t addr) {
    asm volatile("ldmatrix.sync.aligned.m8n8.x4.shared.b16 {%0,%1,%2,%3}, [%4];"
                 : "=r"(r[0]), "=r"(r[1]), "=r"(r[2]), "=r"(r[3]) : "r"(addr));
}
__device__ __forceinline__ void ldsm_x2t(uint32_t* r, uint32_t addr) {
    asm volatile("ldmatrix.sync.aligned.m8n8.x2.trans.shared.b16 {%0,%1}, [%2];"
                 : "=r"(r[0]), "=r"(r[1]) : "r"(addr));
}

// ==================== conversions ===========================================
__global__ void k_cvt_x(const float* __restrict__ x, uint32_t* __restrict__ xb,
                        int n2) {
    int i = blockIdx.x * blockDim.x + threadIdx.x;
    if (i < n2) xb[i] = bf2_pack(x[2 * i], x[2 * i + 1]);
}
// all three weights, elementwise f32 -> bf16 (u32-pair granularity)
__global__ void k_cvt_w3(const float* __restrict__ W0, const float* __restrict__ W1,
                         const float* __restrict__ W2, uint32_t* __restrict__ wb) {
    int i = blockIdx.x * blockDim.x + threadIdx.x;   // 0 .. 196608
    if (i >= 196608) return;
    const float* src;
    int off;
    if (i < 32768)       { src = W0; off = i; }
    else if (i < 163840) { src = W1; off = i - 32768; }
    else                 { src = W2; off = i - 163840; }
    wb[i] = bf2_pack(src[2 * off], src[2 * off + 1]);
}

// ==================== CSR build (count fused with init) =====================
__global__ void k_count_init(const int* __restrict__ ei, int E, int Etot,
                             int* __restrict__ cnt, float* __restrict__ as,
                             float* __restrict__ ad, float* __restrict__ pool,
                             int n) {
    int e = blockIdx.x * blockDim.x + threadIdx.x;
    if (e < n) cnt[e] = 0;
    int tot = 3 * n * NHEADS;
    if (e < tot) { as[e] = 0.f; ad[e] = 0.f; }
    if (e < HIDC) pool[e] = 0.f;
    if (e < Etot) {
        int s, d; edge_sd(ei, E, e, s, d);
        atomicAdd(&cnt[d], 1);
    }
}
__global__ void k_scan(const int* __restrict__ cnt, int* __restrict__ row_ptr,
                       int* __restrict__ cursor, int n) {
    __shared__ int part[1024];
    int t = threadIdx.x;
    int per = (n + 1023) / 1024;
    int begi = t * per;
    int endi = min(n, begi + per);
    int s = 0;
    for (int i = begi; i < endi; i++) s += cnt[i];
    part[t] = s;
    __syncthreads();
    for (int o = 1; o < 1024; o <<= 1) {
        int v = (t >= o) ? part[t - o] : 0;
        __syncthreads();
        part[t] += v;
        __syncthreads();
    }
    int off = t ? part[t - 1] : 0;
    for (int i = begi; i < endi; i++) {
        row_ptr[i] = off; cursor[i] = off;
        off += cnt[i];
    }
    if (t == 1023) row_ptr[n] = part[1023];
}
__global__ void k_scatter(const int* __restrict__ ei, int E, int Etot,
                          int* __restrict__ cursor, int* __restrict__ csr_src) {
    int e = blockIdx.x * blockDim.x + threadIdx.x;
    if (e >= Etot) return;
    int s, d; edge_sd(ei, E, e, s, d);
    int pos = atomicAdd(&cursor[d], 1);
    csr_src[pos] = s;
}

// ==================== cp.async bf16 GEMM (ldmatrix) + attn epilogue =========
// C = A[n,K](bf16) @ Wb[K,M](bf16), mma.m16n8k16, fp32 accum.
// BM=128, BN=64, BK=64, 256 threads, 2-stage cp.async double buffer.
#define BM 128
#define BN 64
#define BK 64
#define AS_STRIDE (BK + 8)                  // bf16 units (72) -> 144 B/row
#define BS_STRIDE (BN + 8)                  // bf16 units (72) -> 144 B/row
#define AS_BYTES (BM * AS_STRIDE * 2)       // 18432
#define BS_BYTES (BK * BS_STRIDE * 2)       // 9216
#define STAGE_BYTES (AS_BYTES + BS_BYTES)   // 27648
#define SMEM_BYTES (2 * STAGE_BYTES)        // 55296

__device__ __forceinline__ void mma_bf16(float* c, const uint32_t* a, const uint32_t* b) {
    asm volatile(
        "mma.sync.aligned.m16n8k16.row.col.f32.bf16.bf16.f32 "
        "{%0,%1,%2,%3}, {%4,%5,%6,%7}, {%8,%9}, {%0,%1,%2,%3};"
        : "+f"(c[0]), "+f"(c[1]), "+f"(c[2]), "+f"(c[3])
        : "r"(a[0]), "r"(a[1]), "r"(a[2]), "r"(a[3]), "r"(b[0]), "r"(b[1]));
}

__global__ __launch_bounds__(256) void k_gemm_fused(
    const __nv_bfloat16* __restrict__ A, const __nv_bfloat16* __restrict__ Wb,
    const float* __restrict__ a_s, const float* __restrict__ a_d,
    __nv_bfloat16* __restrict__ xlh,
    float* __restrict__ as, float* __restrict__ ad,
    int n, int K, int M, int H) {
    extern __shared__ char smem[];
    int tid = threadIdx.x;
    int warp = tid >> 5, lane = tid & 31;
    int gid = lane >> 2, tig = lane & 3;
    int warpM = warp & 3, warpN = warp >> 2;
    int row0 = blockIdx.y * BM, col0 = blockIdx.x * BN;

    float c[2][4][4] = {};

    // A copy: 128 rows x 128B (8 chunks) = 1024 chunks, 4/thread
    int a_r = tid >> 1;            // 0..127 (2 chunk-cols per thread)
    int a_c = (tid & 1) * 4;       // chunk 0-3 or 4-7 pairs... see below
    // B copy: 64 rows x 128B (8 chunks) = 512 chunks, 2/thread
    int b_r = tid >> 2;            // 0..63
    int b_c = (tid & 3) * 2;       // chunk pairs

    auto issue = [&](int kt, int st) {
        char* base = smem + st * STAGE_BYTES;
        // A: thread covers rows a_r, chunks a_c..a_c+3 (4x16B = 64B)
        {
            int grow = row0 + a_r;
            int sz = (grow < n) ? 16 : 0;
            const __nv_bfloat16* gA = A + (size_t)grow * K + kt + a_c * 8;
            uint32_t dst = smem_u32(base + a_r * (AS_STRIDE * 2) + a_c * 16);
#pragma unroll
            for (int q = 0; q < 4; q++)
                cp16(dst + q * 16, gA + q * 8, sz);
        }
        // B: thread covers row b_r, chunks b_c, b_c+1
        {
            char* bbase = base + AS_BYTES;
            const __nv_bfloat16* gB = Wb + (size_t)(kt + b_r) * M + col0 + b_c * 8;
            uint32_t dst = smem_u32(bbase + b_r * (BS_STRIDE * 2) + b_c * 16);
            cp16(dst,      gB,     16);
            cp16(dst + 16, gB + 8, 16);
        }
    };

    auto compute = [&](int st) {
        const __nv_bfloat16* As = (const __nv_bfloat16*)(smem + st * STAGE_BYTES);
        const __nv_bfloat16* Bs = (const __nv_bfloat16*)(smem + st * STAGE_BYTES + AS_BYTES);
#pragma unroll
        for (int kk = 0; kk < BK; kk += 16) {
            uint32_t afr[2][4];
#pragma unroll
            for (int t = 0; t < 2; t++) {
                int m0 = warpM * 32 + t * 16;
                const __nv_bfloat16* ap =
                    As + (m0 + (lane & 15)) * AS_STRIDE + kk + 8 * (lane >> 4);
                ldsm_x4(afr[t], smem_u32(ap));
            }
            uint32_t bfr[4][2];
#pragma unroll
            for (int j = 0; j < 4; j++) {
                int n0 = warpN * 32 + j * 8;
                const __nv_bfloat16* bp = Bs + (kk + (lane & 15)) * BS_STRIDE + n0;
                ldsm_x2t(bfr[j], smem_u32(bp));
            }
#pragma unroll
            for (int i = 0; i < 2; i++)
#pragma unroll
                for (int j = 0; j < 4; j++)
                    mma_bf16(c[i][j], afr[i], bfr[j]);
        }
    };

    int KT = K / BK;
    issue(0, 0);
    cp_commit();
    for (int t = 0; t < KT; t++) {
        int st = t & 1;
        if (t + 1 < KT) {
            issue((t + 1) * BK, st ^ 1);
            cp_commit();
            cp_wait<1>();
        } else {
            cp_wait<0>();
        }
        __syncthreads();
        compute(st);
        __syncthreads();
    }

    // ---- epilogue: bf16 store + fused attention partial dots ----
    int h = col0 / HIDC;
    int inh0 = col0 - h * HIDC;
    float ws[4][2], wd[4][2];
#pragma unroll
    for (int j = 0; j < 4; j++)
#pragma unroll
        for (int q = 0; q < 2; q++) {
            int cc = inh0 + warpN * 32 + j * 8 + tig * 2 + q;
            ws[j][q] = a_s[h * HIDC + cc];
            wd[j][q] = a_d[h * HIDC + cc];
        }
#pragma unroll
    for (int i = 0; i < 2; i++) {
        int r0 = row0 + warpM * 32 + i * 16 + gid;
        float ps0 = 0.f, pd0 = 0.f, ps8 = 0.f, pd8 = 0.f;
#pragma unroll
        for (int j = 0; j < 4; j++) {
            ps0 += c[i][j][0] * ws[j][0] + c[i][j][1] * ws[j][1];
            pd0 += c[i][j][0] * wd[j][0] + c[i][j][1] * wd[j][1];
            ps8 += c[i][j][2] * ws[j][0] + c[i][j][3] * ws[j][1];
            pd8 += c[i][j][2] * wd[j][0] + c[i][j][3] * wd[j][1];
            int cc = col0 + warpN * 32 + j * 8 + tig * 2;
            if (r0 < n) {
                *(uint32_t*)(xlh + (size_t)r0 * M + cc) = bf2_pack(c[i][j][0], c[i][j][1]);
            }
            if (r0 + 8 < n) {
                *(uint32_t*)(xlh + (size_t)(r0 + 8) * M + cc) = bf2_pack(c[i][j][2], c[i][j][3]);
            }
        }
#pragma unroll
        for (int o = 1; o < 4; o <<= 1) {
            ps0 += __shfl_xor_sync(0xffffffffu, ps0, o);
            pd0 += __shfl_xor_sync(0xffffffffu, pd0, o);
            ps8 += __shfl_xor_sync(0xffffffffu, ps8, o);
            pd8 += __shfl_xor_sync(0xffffffffu, pd8, o);
        }
        if (tig == 0) {
            if (r0 < n) {
                atomicAdd(&as[r0 * H + h], ps0);
                atomicAdd(&ad[r0 * H + h], pd0);
            }
            if (r0 + 8 < n) {
                atomicAdd(&as[(r0 + 8) * H + h], ps8);
                atomicAdd(&ad[(r0 + 8) * H + h], pd8);
            }
        }
    }
}

// ==================== fused softmax + bf16 gather aggregate =================
__global__ void k_node_agg(const int* __restrict__ csr_src,
                           const int* __restrict__ row_ptr,
                           const __nv_bfloat16* __restrict__ xlh,
                           const float* __restrict__ as,
                           const float* __restrict__ ad,
                           const float* __restrict__ b,
                           float* __restrict__ outf,
                           uint32_t* __restrict__ outb,
                           int n, int H, int M, int relu) {
    int w = (blockIdx.x * blockDim.x + threadIdx.x) >> 5;
    if (w >= n * H) return;
    int node = w / H, h = w - node * H;
    int lane = threadIdx.x & 31;
    int beg = row_ptr[node], deg = row_ptr[node + 1] - beg;
    float ad_n = ad[node * H + h];

    float m = -3.4e38f;
    for (int i = lane; i < deg; i += 32) {
        int s = csr_src[beg + i];
        float e = as[s * H + h] + ad_n;
        e = e > 0.f ? e : 0.2f * e;
        m = fmaxf(m, e);
    }
#pragma unroll
    for (int o = 16; o; o >>= 1) m = fmaxf(m, __shfl_xor_sync(0xffffffffu, m, o));

    float den = 0.f;
    float a00 = 0.f, a01 = 0.f, a10 = 0.f, a11 = 0.f;
    const uint32_t* xbase = (const uint32_t*)xlh;
    for (int i0 = 0; i0 < deg; i0 += 32) {
        int i = i0 + lane;
        float x = 0.f; int s = 0;
        if (i < deg) {
            s = csr_src[beg + i];
            float e = as[s * H + h] + ad_n;
            e = e > 0.f ? e : 0.2f * e;
            x = __expf(e - m);
            den += x;
        }
        int cnt = min(32, deg - i0);
        for (int j = 0; j < cnt; j++) {
            float xj = __shfl_sync(0xffffffffu, x, j);
            int   sj = __shfl_sync(0xffffffffu, s, j);
            const uint2 u = *(const uint2*)(xbase + (((size_t)sj * M + h * HIDC) >> 1) + 2 * lane);
            a00 += xj * __uint_as_float(u.x << 16);
            a01 += xj * __uint_as_float(u.x & 0xffff0000u);
            a10 += xj * __uint_as_float(u.y << 16);
            a11 += xj * __uint_as_float(u.y & 0xffff0000u);
        }
    }
#pragma unroll
    for (int o = 16; o; o >>= 1) den += __shfl_xor_sync(0xffffffffu, den, o);
    float inv = 1.f / den;

    int c0 = 4 * lane;
    float v0 = a00 * inv + b[h * HIDC + c0];
    float v1 = a01 * inv + b[h * HIDC + c0 + 1];
    float v2 = a10 * inv + b[h * HIDC + c0 + 2];
    float v3 = a11 * inv + b[h * HIDC + c0 + 3];
    if (relu) {
        v0 = fmaxf(v0, 0.f); v1 = fmaxf(v1, 0.f);
        v2 = fmaxf(v2, 0.f); v3 = fmaxf(v3, 0.f);
    }
    size_t base = (size_t)node * M + h * HIDC + c0;
    if (outb) {
        uint2 o2;
        o2.x = bf2_pack(v0, v1);
        o2.y = bf2_pack(v2, v3);
        *(uint2*)(outb + (base >> 1)) = o2;
    } else {
        *(float4*)(outf + base) = make_float4(v0, v1, v2, v3);
    }
}

// ==================== pool + MLP ============================================
__global__ void k_pool(const float* __restrict__ h, float* __restrict__ pool, int n) {
    int t = threadIdx.x;  // 128
    float s = 0.f;
    for (int r = blockIdx.x; r < n; r += gridDim.x)
        s += h[(size_t)r * HIDC + t];
    atomicAdd(&pool[t], s);
}
__global__ void k_mlp(const float* __restrict__ pool, const float* __restrict__ Wm1,
                      const float* __restrict__ bm1, const float* __restrict__ Wm2,
                      const float* __restrict__ bm2, float* __restrict__ out,
                      float invn) {
    __shared__ float g[HIDC];
    __shared__ float t1[HIDC / 2];
    int t = threadIdx.x;  // 128
    g[t] = pool[t] * invn;
    __syncthreads();
    if (t < HIDC / 2) {
        float s = bm1[t];
#pragma unroll 8
        for (int i = 0; i < HIDC; i++) s += g[i] * Wm1[i * (HIDC / 2) + t];
        t1[t] = fmaxf(s, 0.f);
    }
    __syncthreads();
    if (t == 0) {
        float s = bm2[0];
#pragma unroll 8
        for (int j = 0; j < HIDC / 2; j++) s += t1[j] * Wm2[j];
        out[0] = s;
    }
}

// ============================================================================
extern "C" void kernel_launch(void* const* d_in, const int* in_sizes, int n_in,
                              void* d_out, int out_size) {
    const float* x    = (const float*)d_in[0];
    const int*   ei   = (const int*)  d_in[1];
    const float* W0   = (const float*)d_in[2];
    const float* as0  = (const float*)d_in[3];
    const float* ad0  = (const float*)d_in[4];
    const float* b0   = (const float*)d_in[5];
    const float* W1   = (const float*)d_in[6];
    const float* as1  = (const float*)d_in[7];
    const float* ad1  = (const float*)d_in[8];
    const float* b1   = (const float*)d_in[9];
    const float* W2   = (const float*)d_in[10];
    const float* as2  = (const float*)d_in[11];
    const float* ad2  = (const float*)d_in[12];
    const float* b2   = (const float*)d_in[13];
    const float* Wm1  = (const float*)d_in[14];
    const float* bm1  = (const float*)d_in[15];
    const float* Wm2  = (const float*)d_in[16];
    const float* bm2  = (const float*)d_in[17];

    int n = in_sizes[0] / DIN;        // 20000
    int E = in_sizes[1] / 2;          // 320000
    int Etot = E + n;

    float *h1, *asb, *adb, *pool;
    __nv_bfloat16 *xlh, *hb0, *hb1, *xb, *wb;
    int *csr_src, *row_ptr, *cnt, *cursor;
    { void* p;
      cudaGetSymbolAddress(&p, g_h1);      h1      = (float*)p;
      cudaGetSymbolAddress(&p, g_hb0);     hb0     = (__nv_bfloat16*)p;
      cudaGetSymbolAddress(&p, g_hb1);     hb1     = (__nv_bfloat16*)p;
      cudaGetSymbolAddress(&p, g_xb);      xb      = (__nv_bfloat16*)p;
      cudaGetSymbolAddress(&p, g_wb);      wb      = (__nv_bfloat16*)p;
      cudaGetSymbolAddress(&p, g_xlh);     xlh     = (__nv_bfloat16*)p;
      cudaGetSymbolAddress(&p, g_as);      asb     = (float*)p;
      cudaGetSymbolAddress(&p, g_ad);      adb     = (float*)p;
      cudaGetSymbolAddress(&p, g_pool);    pool    = (float*)p;
      cudaGetSymbolAddress(&p, g_csr_src); csr_src = (int*)p;
      cudaGetSymbolAddress(&p, g_row_ptr); row_ptr = (int*)p;
      cudaGetSymbolAddress(&p, g_cnt);     cnt     = (int*)p;
      cudaGetSymbolAddress(&p, g_cursor);  cursor  = (int*)p;
    }

    static bool attr_done = false;
    if (!attr_done) {
        cudaFuncSetAttribute(k_gemm_fused,
                             cudaFuncAttributeMaxDynamicSharedMemorySize, SMEM_BYTES);
        attr_done = true;
    }

    // ---- conversions ----
    __nv_bfloat16* w0b = wb;              // [128,512]
    __nv_bfloat16* w1b = wb + 65536;      // [512,512]
    __nv_bfloat16* w2b = wb + 327680;     // [512,128]
    {
        int n2 = n * DIN / 2;
        k_cvt_x<<<(n2 + 255) / 256, 256>>>(x, (uint32_t*)xb, n2);
        k_cvt_w3<<<(196608 + 255) / 256, 256>>>(W0, W1, W2, (uint32_t*)wb);
    }

    // ---- CSR build + init (fused) ----
    int initN = 3 * n * NHEADS;
    int cgrid = (initN > Etot ? initN : Etot);
    k_count_init<<<(cgrid + 255) / 256, 256>>>(ei, E, Etot, cnt, asb, adb, pool, n);
    k_scan   <<<1, 1024>>>(cnt, row_ptr, cursor, n);
    k_scatter<<<(Etot + 255) / 256, 256>>>(ei, E, Etot, cursor, csr_src);

    auto run_layer = [&](const __nv_bfloat16* in, const __nv_bfloat16* Wp,
                         int K, int H, int layer,
                         const float* a_s, const float* a_d,
                         const float* b, float* outf, uint32_t* outb, int relu) {
        int M = H * HIDC;
        float* asL = asb + (size_t)layer * NN * NHEADS;
        float* adL = adb + (size_t)layer * NN * NHEADS;
        dim3 gg(M / BN, (n + BM - 1) / BM);
        k_gemm_fused<<<gg, 256, SMEM_BYTES>>>(in, Wp, a_s, a_d, xlh, asL, adL,
                                              n, K, M, H);
        int warps = n * H;
        k_node_agg<<<(warps * 32 + 255) / 256, 256>>>(csr_src, row_ptr, xlh,
                                                      asL, adL, b, outf, outb,
                                                      n, H, M, relu);
    };

    run_layer(xb,  w0b, DIN, NHEADS, 0, as0, ad0, b0, nullptr, (uint32_t*)hb0, 1);
    run_layer(hb0, w1b, 512, NHEADS, 1, as1, ad1, b1, nullptr, (uint32_t*)hb1, 1);
    run_layer(hb1, w2b, 512, 1,      2, as2, ad2, b2, h1, nullptr, 0);

    k_pool<<<256, HIDC>>>(h1, pool, n);
    k_mlp<<<1, HIDC>>>(pool, Wm1, bm1, Wm2, bm2, (float*)d_out, 1.f / (float)n);
}

// round 17
// speedup vs baseline: 1.1684x; 1.1684x over previous
#include <cuda_runtime.h>
#include <cuda_bf16.h>
#include <cstdint>

#define NN 20000
#define DIN 128
#define HIDC 128
#define NHEADS 4
#define MAXM (NHEADS * HIDC)      // 512
#define EMAX 320000
#define ETOTMAX (EMAX + NN)

// -------------------- scratch (device globals) ------------------------------
__device__ float         g_h1 [NN * MAXM];            // f32 (final layer out)
__device__ __nv_bfloat16 g_hb0[NN * MAXM];            // bf16 layer outputs
__device__ __nv_bfloat16 g_hb1[NN * MAXM];
__device__ __nv_bfloat16 g_xb [NN * DIN];             // bf16 input x
__device__ uint32_t      g_wpk[196608];               // packed bf16 weights
__device__ __nv_bfloat16 g_xlh[NN * MAXM];
__device__ float         g_as [3 * NN * NHEADS];
__device__ float         g_ad [3 * NN * NHEADS];
__device__ float         g_pool[HIDC];
__device__ int           g_csr_src[ETOTMAX];
__device__ int           g_row_ptr[NN + 1];
__device__ int           g_cnt[NN];
__device__ int           g_cursor[NN];
__device__ int           g_incl[NN];
__device__ int           g_bsum[256];

// -------------------- helpers ----------------------------------------------
__device__ __forceinline__ uint32_t bf2_pack(float lo, float hi) {
    __nv_bfloat162 v = __float22bfloat162_rn(make_float2(lo, hi));
    return *(uint32_t*)&v;
}
__device__ __forceinline__ uint32_t smem_u32(const void* p) {
    return (uint32_t)__cvta_generic_to_shared(p);
}
__device__ __forceinline__ void cp16(uint32_t saddr, const void* g, int srcsz) {
    asm volatile("cp.async.cg.shared.global [%0], [%1], 16, %2;"
                 :: "r"(saddr), "l"(g), "r"(srcsz));
}
__device__ __forceinline__ void cp_commit() {
    asm volatile("cp.async.commit_group;");
}
template <int N> __device__ __forceinline__ void cp_wait() {
    asm volatile("cp.async.wait_group %0;" :: "n"(N));
}
__device__ __forceinline__ void edge_sd(const int* __restrict__ ei, int E, int e,
                                        int& s, int& d) {
    if (e < E) { s = ei[e]; d = ei[E + e]; }
    else       { s = d = e - E; }
}

// ==================== conversions ===========================================
// also zeroes cnt (safely before k_count launch)
__global__ void k_cvt_x(const float* __restrict__ x, uint32_t* __restrict__ xb,
                        int n2, int* __restrict__ cnt, int n) {
    int i = blockIdx.x * blockDim.x + threadIdx.x;
    if (i < n2) xb[i] = bf2_pack(x[2 * i], x[2 * i + 1]);
    if (i < n) cnt[i] = 0;
}
// all three weights -> packed layout Wpk[K/2, M] (bf16 pair of k, k+1 per col m)
__global__ void k_cvt_w3(const float* __restrict__ W0, const float* __restrict__ W1,
                         const float* __restrict__ W2, uint32_t* __restrict__ wpk) {
    int i = blockIdx.x * blockDim.x + threadIdx.x;   // 0 .. 196608
    if (i >= 196608) return;
    const float* W; int off, M;
    if (i < 32768)        { W = W0; off = i;          M = 512; }
    else if (i < 163840)  { W = W1; off = i - 32768;  M = 512; }
    else                  { W = W2; off = i - 163840; M = 128; }
    int kp = off / M, m = off - kp * M;
    wpk[i] = bf2_pack(W[(size_t)(2 * kp) * M + m], W[(size_t)(2 * kp + 1) * M + m]);
}

// ==================== count (+ as/ad/pool init; cnt pre-zeroed) =============
__global__ void k_count(const int* __restrict__ ei, int E, int Etot,
                        int* __restrict__ cnt, float* __restrict__ as,
                        float* __restrict__ ad, float* __restrict__ pool, int n) {
    int e = blockIdx.x * blockDim.x + threadIdx.x;
    int tot = 3 * n * NHEADS;
    if (e < tot) { as[e] = 0.f; ad[e] = 0.f; }
    if (e < HIDC) pool[e] = 0.f;
    if (e < Etot) {
        int s, d; edge_sd(ei, E, e, s, d);
        atomicAdd(&cnt[d], 1);
    }
}

// ==================== multi-block exclusive scan ============================
#define SCB 256
__global__ void k_scan1(const int* __restrict__ cnt, int* __restrict__ incl,
                        int* __restrict__ bsum, int n) {
    __shared__ int sm[SCB];
    int t = threadIdx.x;
    int i = blockIdx.x * SCB + t;
    int v = (i < n) ? cnt[i] : 0;
    sm[t] = v;
    __syncthreads();
#pragma unroll
    for (int o = 1; o < SCB; o <<= 1) {
        int u = (t >= o) ? sm[t - o] : 0;
        __syncthreads();
        sm[t] += u;
        __syncthreads();
    }
    if (i < n) incl[i] = sm[t];
    if (t == SCB - 1) bsum[blockIdx.x] = sm[t];
}
__global__ void k_scan2(int* __restrict__ bsum, int nb) {
    __shared__ int sm[128];
    int t = threadIdx.x;
    sm[t] = (t < nb) ? bsum[t] : 0;
    __syncthreads();
#pragma unroll
    for (int o = 1; o < 128; o <<= 1) {
        int u = (t >= o) ? sm[t - o] : 0;
        __syncthreads();
        sm[t] += u;
        __syncthreads();
    }
    if (t < nb) bsum[t] = sm[t];
}
__global__ void k_scan3(const int* __restrict__ cnt, const int* __restrict__ incl,
                        const int* __restrict__ bsum,
                        int* __restrict__ row_ptr, int* __restrict__ cursor, int n) {
    int b = blockIdx.x;
    int i = b * SCB + threadIdx.x;
    if (i >= n) return;
    int off = b ? bsum[b - 1] : 0;
    int ic = incl[i] + off;
    int ex = ic - cnt[i];
    row_ptr[i] = ex;
    cursor[i] = ex;
    if (i == n - 1) row_ptr[n] = ic;
}
__global__ void k_scatter(const int* __restrict__ ei, int E, int Etot,
                          int* __restrict__ cursor, int* __restrict__ csr_src) {
    int e = blockIdx.x * blockDim.x + threadIdx.x;
    if (e >= Etot) return;
    int s, d; edge_sd(ei, E, e, s, d);
    int pos = atomicAdd(&cursor[d], 1);
    csr_src[pos] = s;
}

// ==================== cp.async bf16 GEMM + attn-dot epilogue ================
// C = A[n,K](bf16) @ Wpk[K/2,M](packed bf16), mma.m16n8k16, fp32 accum.
// BM=128, BN=64, BK=64, 256 threads, 2-stage cp.async double buffer. (R12 proven)
#define BM 128
#define BN 64
#define BK 64
#define AS_STRIDE (BK + 8)                 // bf16 units (72) -> 144 B/row
#define BS_STRIDE (BN + 8)                 // u32 units (72)  -> 288 B/row
#define AS_BYTES (BM * AS_STRIDE * 2)      // 18432
#define BS_BYTES ((BK / 2) * BS_STRIDE * 4) // 9216
#define STAGE_BYTES (AS_BYTES + BS_BYTES)
#define SMEM_BYTES (2 * STAGE_BYTES)       // 55296

__device__ __forceinline__ void mma_bf16(float* c, const uint32_t* a, const uint32_t* b) {
    asm volatile(
        "mma.sync.aligned.m16n8k16.row.col.f32.bf16.bf16.f32 "
        "{%0,%1,%2,%3}, {%4,%5,%6,%7}, {%8,%9}, {%0,%1,%2,%3};"
        : "+f"(c[0]), "+f"(c[1]), "+f"(c[2]), "+f"(c[3])
        : "r"(a[0]), "r"(a[1]), "r"(a[2]), "r"(a[3]), "r"(b[0]), "r"(b[1]));
}

__global__ __launch_bounds__(256) void k_gemm_fused(
    const __nv_bfloat16* __restrict__ A, const uint32_t* __restrict__ Wpk,
    const float* __restrict__ a_s, const float* __restrict__ a_d,
    __nv_bfloat16* __restrict__ xlh,
    float* __restrict__ as, float* __restrict__ ad,
    int n, int K, int M, int H) {
    extern __shared__ char smem[];
    int tid = threadIdx.x;
    int warp = tid >> 5, lane = tid & 31;
    int gid = lane >> 2, tig = lane & 3;
    int warpM = warp & 3, warpN = warp >> 2;
    int row0 = blockIdx.y * BM, col0 = blockIdx.x * BN;

    float c[2][4][4] = {};

    int a_r = tid >> 3;            // 0..31 (+32 per pass, 4 passes)
    int a_c = (tid & 7) * 8;       // bf16 k-offset, 16B chunks
    int b_r = tid >> 4;            // 0..15 (+16, 2 passes)
    int b_c = (tid & 15) * 4;      // u32 n-offset, 16B chunks

    auto issue = [&](int kt, int st) {
        char* base = smem + st * STAGE_BYTES;
#pragma unroll
        for (int p = 0; p < 4; p++) {
            int r = a_r + p * 32;
            int grow = row0 + r;
            int sz = (grow < n) ? 16 : 0;
            const __nv_bfloat16* gA = A + (size_t)grow * K + kt + a_c;
            cp16(smem_u32(base + r * (AS_STRIDE * 2) + a_c * 2), gA, sz);
        }
        char* bbase = base + AS_BYTES;
        int ktp = kt >> 1;
#pragma unroll
        for (int p = 0; p < 2; p++) {
            int r = b_r + p * 16;
            const uint32_t* gB = Wpk + (size_t)(ktp + r) * M + col0 + b_c;
            cp16(smem_u32(bbase + r * (BS_STRIDE * 4) + b_c * 4), gB, 16);
        }
    };

    auto compute = [&](int st) {
        const __nv_bfloat16* As = (const __nv_bfloat16*)(smem + st * STAGE_BYTES);
        const uint32_t* Bs = (const uint32_t*)(smem + st * STAGE_BYTES + AS_BYTES);
#pragma unroll
        for (int kk = 0; kk < BK; kk += 16) {
            uint32_t afr[2][4];
#pragma unroll
            for (int t = 0; t < 2; t++) {
                int m = warpM * 32 + t * 16 + gid;
                int k0 = kk + 2 * tig;
                const __nv_bfloat16* rm = As + m * AS_STRIDE;
                const __nv_bfloat16* rm8 = As + (m + 8) * AS_STRIDE;
                afr[t][0] = *(const uint32_t*)(rm + k0);
                afr[t][1] = *(const uint32_t*)(rm8 + k0);
                afr[t][2] = *(const uint32_t*)(rm + k0 + 8);
                afr[t][3] = *(const uint32_t*)(rm8 + k0 + 8);
            }
            uint32_t bfr[4][2];
            int kp0 = (kk >> 1) + tig;
#pragma unroll
            for (int t = 0; t < 4; t++) {
                int nn2 = warpN * 32 + t * 8 + gid;
                bfr[t][0] = Bs[kp0 * BS_STRIDE + nn2];
                bfr[t][1] = Bs[(kp0 + 4) * BS_STRIDE + nn2];
            }
#pragma unroll
            for (int i = 0; i < 2; i++)
#pragma unroll
                for (int j = 0; j < 4; j++)
                    mma_bf16(c[i][j], afr[i], bfr[j]);
        }
    };

    int KT = K / BK;
    issue(0, 0);
    cp_commit();
    for (int t = 0; t < KT; t++) {
        int st = t & 1;
        if (t + 1 < KT) {
            issue((t + 1) * BK, st ^ 1);
            cp_commit();
            cp_wait<1>();
        } else {
            cp_wait<0>();
        }
        __syncthreads();
        compute(st);
        __syncthreads();
    }

    // ---- epilogue: bf16 store + fused attention partial dots ----
    int h = col0 / HIDC;
    int inh0 = col0 - h * HIDC;
    float ws[4][2], wd[4][2];
#pragma unroll
    for (int j = 0; j < 4; j++)
#pragma unroll
        for (int q = 0; q < 2; q++) {
            int cc = inh0 + warpN * 32 + j * 8 + tig * 2 + q;
            ws[j][q] = a_s[h * HIDC + cc];
            wd[j][q] = a_d[h * HIDC + cc];
        }
#pragma unroll
    for (int i = 0; i < 2; i++) {
        int r0 = row0 + warpM * 32 + i * 16 + gid;
        float ps0 = 0.f, pd0 = 0.f, ps8 = 0.f, pd8 = 0.f;
#pragma unroll
        for (int j = 0; j < 4; j++) {
            ps0 += c[i][j][0] * ws[j][0] + c[i][j][1] * ws[j][1];
            pd0 += c[i][j][0] * wd[j][0] + c[i][j][1] * wd[j][1];
            ps8 += c[i][j][2] * ws[j][0] + c[i][j][3] * ws[j][1];
            pd8 += c[i][j][2] * wd[j][0] + c[i][j][3] * wd[j][1];
            int cc = col0 + warpN * 32 + j * 8 + tig * 2;
            if (r0 < n) {
                *(uint32_t*)(xlh + (size_t)r0 * M + cc) = bf2_pack(c[i][j][0], c[i][j][1]);
            }
            if (r0 + 8 < n) {
                *(uint32_t*)(xlh + (size_t)(r0 + 8) * M + cc) = bf2_pack(c[i][j][2], c[i][j][3]);
            }
        }
#pragma unroll
        for (int o = 1; o < 4; o <<= 1) {
            ps0 += __shfl_xor_sync(0xffffffffu, ps0, o);
            pd0 += __shfl_xor_sync(0xffffffffu, pd0, o);
            ps8 += __shfl_xor_sync(0xffffffffu, ps8, o);
            pd8 += __shfl_xor_sync(0xffffffffu, pd8, o);
        }
        if (tig == 0) {
            if (r0 < n) {
                atomicAdd(&as[r0 * H + h], ps0);
                atomicAdd(&ad[r0 * H + h], pd0);
            }
            if (r0 + 8 < n) {
                atomicAdd(&as[(r0 + 8) * H + h], ps8);
                atomicAdd(&ad[(r0 + 8) * H + h], pd8);
            }
        }
    }
}

// ==================== fused softmax + bf16 gather aggregate =================
__global__ void k_node_agg(const int* __restrict__ csr_src,
                           const int* __restrict__ row_ptr,
                           const __nv_bfloat16* __restrict__ xlh,
                           const float* __restrict__ as,
                           const float* __restrict__ ad,
                           const float* __restrict__ b,
                           float* __restrict__ outf,
                           uint32_t* __restrict__ outb,
                           int n, int H, int M, int relu) {
    int w = (blockIdx.x * blockDim.x + threadIdx.x) >> 5;
    if (w >= n * H) return;
    int node = w / H, h = w - node * H;
    int lane = threadIdx.x & 31;
    int beg = row_ptr[node], deg = row_ptr[node + 1] - beg;
    float ad_n = ad[node * H + h];

    float m = -3.4e38f;
    for (int i = lane; i < deg; i += 32) {
        int s = csr_src[beg + i];
        float e = as[s * H + h] + ad_n;
        e = e > 0.f ? e : 0.2f * e;
        m = fmaxf(m, e);
    }
#pragma unroll
    for (int o = 16; o; o >>= 1) m = fmaxf(m, __shfl_xor_sync(0xffffffffu, m, o));

    float den = 0.f;
    float a00 = 0.f, a01 = 0.f, a10 = 0.f, a11 = 0.f;
    const uint32_t* xbase = (const uint32_t*)xlh;
    for (int i0 = 0; i0 < deg; i0 += 32) {
        int i = i0 + lane;
        float x = 0.f; int s = 0;
        if (i < deg) {
            s = csr_src[beg + i];
            float e = as[s * H + h] + ad_n;
            e = e > 0.f ? e : 0.2f * e;
            x = __expf(e - m);
            den += x;
        }
        int cnt = min(32, deg - i0);
        for (int j = 0; j < cnt; j++) {
            float xj = __shfl_sync(0xffffffffu, x, j);
            int   sj = __shfl_sync(0xffffffffu, s, j);
            const uint2 u = *(const uint2*)(xbase + (((size_t)sj * M + h * HIDC) >> 1) + 2 * lane);
            a00 += xj * __uint_as_float(u.x << 16);
            a01 += xj * __uint_as_float(u.x & 0xffff0000u);
            a10 += xj * __uint_as_float(u.y << 16);
            a11 += xj * __uint_as_float(u.y & 0xffff0000u);
        }
    }
#pragma unroll
    for (int o = 16; o; o >>= 1) den += __shfl_xor_sync(0xffffffffu, den, o);
    float inv = 1.f / den;

    int c0 = 4 * lane;
    float v0 = a00 * inv + b[h * HIDC + c0];
    float v1 = a01 * inv + b[h * HIDC + c0 + 1];
    float v2 = a10 * inv + b[h * HIDC + c0 + 2];
    float v3 = a11 * inv + b[h * HIDC + c0 + 3];
    if (relu) {
        v0 = fmaxf(v0, 0.f); v1 = fmaxf(v1, 0.f);
        v2 = fmaxf(v2, 0.f); v3 = fmaxf(v3, 0.f);
    }
    size_t base = (size_t)node * M + h * HIDC + c0;
    if (outb) {
        uint2 o2;
        o2.x = bf2_pack(v0, v1);
        o2.y = bf2_pack(v2, v3);
        *(uint2*)(outb + (base >> 1)) = o2;
    } else {
        *(float4*)(outf + base) = make_float4(v0, v1, v2, v3);
    }
}

// ==================== pool + MLP ============================================
__global__ void k_pool(const float* __restrict__ h, float* __restrict__ pool, int n) {
    int t = threadIdx.x;  // 128
    float s = 0.f;
    for (int r = blockIdx.x; r < n; r += gridDim.x)
        s += h[(size_t)r * HIDC + t];
    atomicAdd(&pool[t], s);
}
__global__ void k_mlp(const float* __restrict__ pool, const float* __restrict__ Wm1,
                      const float* __restrict__ bm1, const float* __restrict__ Wm2,
                      const float* __restrict__ bm2, float* __restrict__ out,
                      float invn) {
    __shared__ float g[HIDC];
    __shared__ float t1[HIDC / 2];
    int t = threadIdx.x;  // 128
    g[t] = pool[t] * invn;
    __syncthreads();
    if (t < HIDC / 2) {
        float s = bm1[t];
#pragma unroll 8
        for (int i = 0; i < HIDC; i++) s += g[i] * Wm1[i * (HIDC / 2) + t];
        t1[t] = fmaxf(s, 0.f);
    }
    __syncthreads();
    if (t == 0) {
        float s = bm2[0];
#pragma unroll 8
        for (int j = 0; j < HIDC / 2; j++) s += t1[j] * Wm2[j];
        out[0] = s;
    }
}

// ============================================================================
extern "C" void kernel_launch(void* const* d_in, const int* in_sizes, int n_in,
                              void* d_out, int out_size) {
    const float* x    = (const float*)d_in[0];
    const int*   ei   = (const int*)  d_in[1];
    const float* W0   = (const float*)d_in[2];
    const float* as0  = (const float*)d_in[3];
    const float* ad0  = (const float*)d_in[4];
    const float* b0   = (const float*)d_in[5];
    const float* W1   = (const float*)d_in[6];
    const float* as1  = (const float*)d_in[7];
    const float* ad1  = (const float*)d_in[8];
    const float* b1   = (const float*)d_in[9];
    const float* W2   = (const float*)d_in[10];
    const float* as2  = (const float*)d_in[11];
    const float* ad2  = (const float*)d_in[12];
    const float* b2   = (const float*)d_in[13];
    const float* Wm1  = (const float*)d_in[14];
    const float* bm1  = (const float*)d_in[15];
    const float* Wm2  = (const float*)d_in[16];
    const float* bm2  = (const float*)d_in[17];

    int n = in_sizes[0] / DIN;        // 20000
    int E = in_sizes[1] / 2;          // 320000
    int Etot = E + n;

    float *h1, *asb, *adb, *pool;
    __nv_bfloat16 *xlh, *hb0, *hb1, *xb;
    uint32_t* wpk;
    int *csr_src, *row_ptr, *cnt, *cursor, *incl, *bsum;
    { void* p;
      cudaGetSymbolAddress(&p, g_h1);      h1      = (float*)p;
      cudaGetSymbolAddress(&p, g_hb0);     hb0     = (__nv_bfloat16*)p;
      cudaGetSymbolAddress(&p, g_hb1);     hb1     = (__nv_bfloat16*)p;
      cudaGetSymbolAddress(&p, g_xb);      xb      = (__nv_bfloat16*)p;
      cudaGetSymbolAddress(&p, g_wpk);     wpk     = (uint32_t*)p;
      cudaGetSymbolAddress(&p, g_xlh);     xlh     = (__nv_bfloat16*)p;
      cudaGetSymbolAddress(&p, g_as);      asb     = (float*)p;
      cudaGetSymbolAddress(&p, g_ad);      adb     = (float*)p;
      cudaGetSymbolAddress(&p, g_pool);    pool    = (float*)p;
      cudaGetSymbolAddress(&p, g_csr_src); csr_src = (int*)p;
      cudaGetSymbolAddress(&p, g_row_ptr); row_ptr = (int*)p;
      cudaGetSymbolAddress(&p, g_cnt);     cnt     = (int*)p;
      cudaGetSymbolAddress(&p, g_cursor);  cursor  = (int*)p;
      cudaGetSymbolAddress(&p, g_incl);    incl    = (int*)p;
      cudaGetSymbolAddress(&p, g_bsum);    bsum    = (int*)p;
    }

    static bool attr_done = false;
    if (!attr_done) {
        cudaFuncSetAttribute(k_gemm_fused,
                             cudaFuncAttributeMaxDynamicSharedMemorySize, SMEM_BYTES);
        attr_done = true;
    }

    // ---- conversions (+ cnt zeroing, safely before k_count) ----
    uint32_t* w0p = wpk;                       // [64,512]
    uint32_t* w1p = wpk + 32768;               // [256,512]
    uint32_t* w2p = w1p + 131072;              // [256,128]
    {
        int n2 = n * DIN / 2;
        k_cvt_x<<<(n2 + 255) / 256, 256>>>(x, (uint32_t*)xb, n2, cnt, n);
        k_cvt_w3<<<(196608 + 255) / 256, 256>>>(W0, W1, W2, wpk);
    }

    // ---- CSR build ----
    int initN = 3 * n * NHEADS;                // 240000
    int cgrid = (initN > Etot ? initN : Etot);
    k_count<<<(cgrid + 255) / 256, 256>>>(ei, E, Etot, cnt, asb, adb, pool, n);
    int nb = (n + SCB - 1) / SCB;              // 79
    k_scan1<<<nb, SCB>>>(cnt, incl, bsum, n);
    k_scan2<<<1, 128>>>(bsum, nb);
    k_scan3<<<nb, SCB>>>(cnt, incl, bsum, row_ptr, cursor, n);
    k_scatter<<<(Etot + 255) / 256, 256>>>(ei, E, Etot, cursor, csr_src);

    auto run_layer = [&](const __nv_bfloat16* in, const uint32_t* Wp, int K, int H,
                         int layer, const float* a_s, const float* a_d,
                         const float* b, float* outf, uint32_t* outb, int relu) {
        int M = H * HIDC;
        float* asL = asb + (size_t)layer * NN * NHEADS;
        float* adL = adb + (size_t)layer * NN * NHEADS;
        dim3 gg(M / BN, (n + BM - 1) / BM);
        k_gemm_fused<<<gg, 256, SMEM_BYTES>>>(in, Wp, a_s, a_d, xlh, asL, adL,
                                              n, K, M, H);
        int warps = n * H;
        k_node_agg<<<(warps * 32 + 255) / 256, 256>>>(csr_src, row_ptr, xlh,
                                                      asL, adL, b, outf, outb,
                                                      n, H, M, relu);
    };

    run_layer(xb,  w0p, DIN,         NHEADS, 0, as0, ad0, b0, nullptr, (uint32_t*)hb0, 1);
    run_layer(hb0, w1p, NHEADS*HIDC, NHEADS, 1, as1, ad1, b1, nullptr, (uint32_t*)hb1, 1);
    run_layer(hb1, w2p, NHEADS*HIDC, 1,      2, as2, ad2, b2, h1, nullptr, 0);

    k_pool<<<256, HIDC>>>(h1, pool, n);
    k_mlp<<<1, HIDC>>>(pool, Wm1, bm1, Wm2, bm2, (float*)d_out, 1.f / (float)n);
}